// round 2
// baseline (speedup 1.0000x reference)
#include <cuda_runtime.h>

#define NSEQ 2048
#define DMODEL 256
#define NH 8
#define DH 32
#define NB 2
#define BNROWS (NB * NSEQ)   // 4096

// ---------------- device scratch (no allocations allowed) ----------------
__device__ float g_Q[NB * NH * NSEQ * DH];   // (b,h,n,dh)
__device__ float g_K[NB * NH * NSEQ * DH];
__device__ float g_V[NB * NH * NSEQ * DH];
__device__ float g_att[NB * NSEQ * DMODEL];  // (b,n,D) pre-output-proj

// ---------------------------------------------------------------------------
// Kernel 1: QKV projections.  Y = x @ W^T + b, written in (b,h,n,dh) layout.
// Grid (BNROWS/64, DMODEL/64, 3), block 256. 64x64 tile, 4x4 micro-tile.
// ---------------------------------------------------------------------------
__global__ __launch_bounds__(256) void qkv_proj_kernel(
    const float* __restrict__ x,
    const float* __restrict__ Wq, const float* __restrict__ bq,
    const float* __restrict__ Wk, const float* __restrict__ bk,
    const float* __restrict__ Wv, const float* __restrict__ bv)
{
    __shared__ float XsT[16][68];   // [k][row]
    __shared__ float WsT[16][68];   // [k][col]

    const float* W; const float* bias; float* dst;
    int z = blockIdx.z;
    if (z == 0)      { W = Wq; bias = bq; dst = g_Q; }
    else if (z == 1) { W = Wk; bias = bk; dst = g_K; }
    else             { W = Wv; bias = bv; dst = g_V; }

    const int i0 = blockIdx.x * 64;
    const int j0 = blockIdx.y * 64;
    const int t  = threadIdx.x;
    const int tx = t & 15, ty = t >> 4;
    const int lr = t >> 2, lk4 = (t & 3) * 4;

    float c[4][4];
    #pragma unroll
    for (int a = 0; a < 4; ++a)
        #pragma unroll
        for (int bb = 0; bb < 4; ++bb) c[a][bb] = 0.f;

    for (int kk = 0; kk < DMODEL; kk += 16) {
        float4 xa = *(const float4*)&x[(size_t)(i0 + lr) * DMODEL + kk + lk4];
        float4 wa = *(const float4*)&W[(size_t)(j0 + lr) * DMODEL + kk + lk4];
        XsT[lk4+0][lr] = xa.x; XsT[lk4+1][lr] = xa.y;
        XsT[lk4+2][lr] = xa.z; XsT[lk4+3][lr] = xa.w;
        WsT[lk4+0][lr] = wa.x; WsT[lk4+1][lr] = wa.y;
        WsT[lk4+2][lr] = wa.z; WsT[lk4+3][lr] = wa.w;
        __syncthreads();
        #pragma unroll
        for (int k = 0; k < 16; ++k) {
            float4 a4 = *(const float4*)&XsT[k][ty * 4];
            float4 b4 = *(const float4*)&WsT[k][tx * 4];
            float av[4] = {a4.x, a4.y, a4.z, a4.w};
            float bv4[4] = {b4.x, b4.y, b4.z, b4.w};
            #pragma unroll
            for (int ii = 0; ii < 4; ++ii)
                #pragma unroll
                for (int jj = 0; jj < 4; ++jj)
                    c[ii][jj] = fmaf(av[ii], bv4[jj], c[ii][jj]);
        }
        __syncthreads();
    }

    #pragma unroll
    for (int ii = 0; ii < 4; ++ii) {
        int i = i0 + ty * 4 + ii;
        int bb = i >> 11;               // batch
        int n  = i & (NSEQ - 1);
        #pragma unroll
        for (int jj = 0; jj < 4; ++jj) {
            int j  = j0 + tx * 4 + jj;
            int hh = j >> 5;
            int dc = j & (DH - 1);
            dst[(((size_t)bb * NH + hh) * NSEQ + n) * DH + dc] = c[ii][jj] + bias[j];
        }
    }
}

// ---------------------------------------------------------------------------
// Kernel 2: fused flash attention with on-the-fly edge-bias MLP.
// Grid (NSEQ/64, NH, NB), block 256.
// Block handles 64 query rows of one (b,h); streams 32-key tiles.
// Thread t: S rows r = t/4; col group (t%4)*8 (for both S cols and dh cols).
//
// Bias MLP collapsed via lrelu(z) = 0.505*z + 0.495*|z| (exact):
//   bias(a) = C0h + C1h*a + sum_k d_k * |fma(a, w1_k, b1_k)|
// ---------------------------------------------------------------------------
__global__ __launch_bounds__(256) void attn_kernel(
    const float* __restrict__ A,
    const float* __restrict__ W1, const float* __restrict__ b1,
    const float* __restrict__ W2, const float* __restrict__ b2)
{
    __shared__ float Qs[64][36];   // [row][d]
    __shared__ float Kt[32][36];   // [d][m]   (K transposed)
    __shared__ float Vs[32][36];   // [m][d]
    __shared__ float Ps[64][36];   // [row][m] softmaxed probs

    const int qb = blockIdx.x, h = blockIdx.y, b = blockIdx.z;
    const int bh = b * NH + h;
    const int q0 = qb * 64;

    const float* Qg = g_Q + (size_t)bh * NSEQ * DH;
    const float* Kg = g_K + (size_t)bh * NSEQ * DH;
    const float* Vg = g_V + (size_t)bh * NSEQ * DH;
    const float* Ab = A + (size_t)b * NSEQ * NSEQ;

    const int t  = threadIdx.x;
    const int r  = t >> 2;
    const int c0 = (t & 3) * 8;

    // Load Q tile (2048 floats)
    {
        int rr = t >> 3, d4 = (t & 7) * 4;
        #pragma unroll
        for (int it = 0; it < 2; ++it) {
            float4 v = *(const float4*)&Qg[(size_t)(q0 + rr + it * 32) * DH + d4];
            *(float4*)&Qs[rr + it * 32][d4] = v;
        }
    }

    // Bias-MLP parameters, collapsed form
    float w1r[8], b1r[8], dkr[8];
    float C0 = b2[h], C1 = 0.f;
    #pragma unroll
    for (int k = 0; k < 8; ++k) {
        float w1k = W1[k], b1k = b1[k], w2k = W2[h * NH + k];
        w1r[k] = w1k; b1r[k] = b1k;
        dkr[k] = 0.495f * w2k;
        C1 = fmaf(0.505f * w2k, w1k, C1);
        C0 = fmaf(0.505f * w2k, b1k, C0);
    }
    const float scale = 0.17677669529663687f;  // 1/sqrt(32)

    float mrow = -3.4e38f, lrow = 0.f;
    float acc[8];
    #pragma unroll
    for (int j = 0; j < 8; ++j) acc[j] = 0.f;

    for (int m0 = 0; m0 < NSEQ; m0 += 32) {
        __syncthreads();   // prev GEMM2 done reading Ps/Vs (and Qs write visible at m0=0)
        {   // load K (transposed) + V tiles
            int m = t >> 3, d4 = (t & 7) * 4;
            float4 kv = *(const float4*)&Kg[(size_t)(m0 + m) * DH + d4];
            Kt[d4 + 0][m] = kv.x; Kt[d4 + 1][m] = kv.y;
            Kt[d4 + 2][m] = kv.z; Kt[d4 + 3][m] = kv.w;
            float4 vv = *(const float4*)&Vg[(size_t)(m0 + m) * DH + d4];
            *(float4*)&Vs[m][d4] = vv;
        }
        __syncthreads();

        // ---- S = Q K^T (each thread: 1 row x 8 cols) ----
        float s[8];
        #pragma unroll
        for (int j = 0; j < 8; ++j) s[j] = 0.f;
        #pragma unroll
        for (int d = 0; d < DH; d += 4) {
            float4 q4 = *(const float4*)&Qs[r][d];
            float qa[4] = {q4.x, q4.y, q4.z, q4.w};
            #pragma unroll
            for (int dd = 0; dd < 4; ++dd) {
                float4 k0 = *(const float4*)&Kt[d + dd][c0];
                float4 k1 = *(const float4*)&Kt[d + dd][c0 + 4];
                s[0] = fmaf(qa[dd], k0.x, s[0]);
                s[1] = fmaf(qa[dd], k0.y, s[1]);
                s[2] = fmaf(qa[dd], k0.z, s[2]);
                s[3] = fmaf(qa[dd], k0.w, s[3]);
                s[4] = fmaf(qa[dd], k1.x, s[4]);
                s[5] = fmaf(qa[dd], k1.y, s[5]);
                s[6] = fmaf(qa[dd], k1.z, s[6]);
                s[7] = fmaf(qa[dd], k1.w, s[7]);
            }
        }

        // ---- edge-bias MLP (collapsed), read A straight to registers ----
        const float* Ap = Ab + (size_t)(q0 + r) * NSEQ + m0 + c0;
        float4 a0 = *(const float4*)&Ap[0];
        float4 a1 = *(const float4*)&Ap[4];
        float av[8] = {a0.x, a0.y, a0.z, a0.w, a1.x, a1.y, a1.z, a1.w};
        #pragma unroll
        for (int j = 0; j < 8; ++j) {
            float a = av[j];
            float bia = fmaf(a, C1, C0);
            #pragma unroll
            for (int k = 0; k < 8; ++k) {
                float zz = fmaf(a, w1r[k], b1r[k]);
                bia = fmaf(dkr[k], fabsf(zz), bia);
            }
            s[j] = fmaf(s[j], scale, bia);
        }

        // ---- online softmax (4 threads per row cooperate via shfl) ----
        float tmax = s[0];
        #pragma unroll
        for (int j = 1; j < 8; ++j) tmax = fmaxf(tmax, s[j]);
        tmax = fmaxf(tmax, __shfl_xor_sync(0xffffffffu, tmax, 1));
        tmax = fmaxf(tmax, __shfl_xor_sync(0xffffffffu, tmax, 2));
        float mnew  = fmaxf(mrow, tmax);
        float alpha = __expf(mrow - mnew);
        float tsum = 0.f;
        #pragma unroll
        for (int j = 0; j < 8; ++j) { s[j] = __expf(s[j] - mnew); tsum += s[j]; }
        tsum += __shfl_xor_sync(0xffffffffu, tsum, 1);
        tsum += __shfl_xor_sync(0xffffffffu, tsum, 2);
        lrow = lrow * alpha + tsum;
        mrow = mnew;
        #pragma unroll
        for (int j = 0; j < 8; ++j) acc[j] *= alpha;

        *(float4*)&Ps[r][c0]     = make_float4(s[0], s[1], s[2], s[3]);
        *(float4*)&Ps[r][c0 + 4] = make_float4(s[4], s[5], s[6], s[7]);
        __syncthreads();

        // ---- O += P V (each thread: 1 row x 8 dh cols) ----
        #pragma unroll
        for (int m = 0; m < 32; m += 4) {
            float4 p4 = *(const float4*)&Ps[r][m];
            float pa[4] = {p4.x, p4.y, p4.z, p4.w};
            #pragma unroll
            for (int mm = 0; mm < 4; ++mm) {
                float4 v0 = *(const float4*)&Vs[m + mm][c0];
                float4 v1 = *(const float4*)&Vs[m + mm][c0 + 4];
                acc[0] = fmaf(pa[mm], v0.x, acc[0]);
                acc[1] = fmaf(pa[mm], v0.y, acc[1]);
                acc[2] = fmaf(pa[mm], v0.z, acc[2]);
                acc[3] = fmaf(pa[mm], v0.w, acc[3]);
                acc[4] = fmaf(pa[mm], v1.x, acc[4]);
                acc[5] = fmaf(pa[mm], v1.y, acc[5]);
                acc[6] = fmaf(pa[mm], v1.z, acc[6]);
                acc[7] = fmaf(pa[mm], v1.w, acc[7]);
            }
        }
    }

    // epilogue: normalize, write (b,n,D) layout for the output projection
    float inv = 1.f / lrow;
    float* op = g_att + ((size_t)b * NSEQ + q0 + r) * DMODEL + h * DH + c0;
    *(float4*)&op[0] = make_float4(acc[0]*inv, acc[1]*inv, acc[2]*inv, acc[3]*inv);
    *(float4*)&op[4] = make_float4(acc[4]*inv, acc[5]*inv, acc[6]*inv, acc[7]*inv);
}

// ---------------------------------------------------------------------------
// Kernel 3: output projection.  out = att @ Wo^T + bo.
// Grid (BNROWS/64, DMODEL/64), block 256.
// ---------------------------------------------------------------------------
__global__ __launch_bounds__(256) void out_proj_kernel(
    const float* __restrict__ Wo, const float* __restrict__ bo,
    float* __restrict__ out)
{
    __shared__ float XsT[16][68];
    __shared__ float WsT[16][68];

    const int i0 = blockIdx.x * 64;
    const int j0 = blockIdx.y * 64;
    const int t  = threadIdx.x;
    const int tx = t & 15, ty = t >> 4;
    const int lr = t >> 2, lk4 = (t & 3) * 4;

    float c[4][4];
    #pragma unroll
    for (int a = 0; a < 4; ++a)
        #pragma unroll
        for (int bb = 0; bb < 4; ++bb) c[a][bb] = 0.f;

    for (int kk = 0; kk < DMODEL; kk += 16) {
        float4 xa = *(const float4*)&g_att[(size_t)(i0 + lr) * DMODEL + kk + lk4];
        float4 wa = *(const float4*)&Wo[(size_t)(j0 + lr) * DMODEL + kk + lk4];
        XsT[lk4+0][lr] = xa.x; XsT[lk4+1][lr] = xa.y;
        XsT[lk4+2][lr] = xa.z; XsT[lk4+3][lr] = xa.w;
        WsT[lk4+0][lr] = wa.x; WsT[lk4+1][lr] = wa.y;
        WsT[lk4+2][lr] = wa.z; WsT[lk4+3][lr] = wa.w;
        __syncthreads();
        #pragma unroll
        for (int k = 0; k < 16; ++k) {
            float4 a4 = *(const float4*)&XsT[k][ty * 4];
            float4 b4 = *(const float4*)&WsT[k][tx * 4];
            float av[4] = {a4.x, a4.y, a4.z, a4.w};
            float bv4[4] = {b4.x, b4.y, b4.z, b4.w};
            #pragma unroll
            for (int ii = 0; ii < 4; ++ii)
                #pragma unroll
                for (int jj = 0; jj < 4; ++jj)
                    c[ii][jj] = fmaf(av[ii], bv4[jj], c[ii][jj]);
        }
        __syncthreads();
    }

    #pragma unroll
    for (int ii = 0; ii < 4; ++ii) {
        int i = i0 + ty * 4 + ii;
        #pragma unroll
        for (int jj = 0; jj < 4; ++jj) {
            int j = j0 + tx * 4 + jj;
            out[(size_t)i * DMODEL + j] = c[ii][jj] + bo[j];
        }
    }
}

// ---------------------------------------------------------------------------
extern "C" void kernel_launch(void* const* d_in, const int* in_sizes, int n_in,
                              void* d_out, int out_size)
{
    const float* x  = (const float*)d_in[0];
    const float* A  = (const float*)d_in[1];
    const float* Wq = (const float*)d_in[2];
    const float* bq = (const float*)d_in[3];
    const float* Wk = (const float*)d_in[4];
    const float* bk = (const float*)d_in[5];
    const float* Wv = (const float*)d_in[6];
    const float* bv = (const float*)d_in[7];
    const float* Wo = (const float*)d_in[8];
    const float* bo = (const float*)d_in[9];
    const float* W1 = (const float*)d_in[10];
    const float* b1 = (const float*)d_in[11];
    const float* W2 = (const float*)d_in[12];
    const float* b2 = (const float*)d_in[13];
    float* out = (float*)d_out;

    dim3 gProj(BNROWS / 64, DMODEL / 64, 3);
    qkv_proj_kernel<<<gProj, 256>>>(x, Wq, bq, Wk, bk, Wv, bv);

    dim3 gAttn(NSEQ / 64, NH, NB);
    attn_kernel<<<gAttn, 256>>>(A, W1, b1, W2, b2);

    dim3 gOut(BNROWS / 64, DMODEL / 64);
    out_proj_kernel<<<gOut, 256>>>(Wo, bo, out);
}

// round 4
// speedup vs baseline: 1.4841x; 1.4841x over previous
#include <cuda_runtime.h>

#define NSEQ 2048
#define DMODEL 256
#define NH 8
#define DH 32
#define NB 2
#define BNROWS (NB * NSEQ)   // 4096

// ---------------- device scratch (no allocations allowed) ----------------
__device__ float g_Q[NB * NH * NSEQ * DH];   // (b,h,n,dh)
__device__ float g_K[NB * NH * NSEQ * DH];
__device__ float g_V[NB * NH * NSEQ * DH];
__device__ float g_att[NB * NSEQ * DMODEL];  // (b,n,D) pre-output-proj

// ---------------------------------------------------------------------------
// Kernel 1: QKV projections.  Y = x @ W^T + b, written in (b,h,n,dh) layout.
// ---------------------------------------------------------------------------
__global__ __launch_bounds__(256) void qkv_proj_kernel(
    const float* __restrict__ x,
    const float* __restrict__ Wq, const float* __restrict__ bq,
    const float* __restrict__ Wk, const float* __restrict__ bk,
    const float* __restrict__ Wv, const float* __restrict__ bv)
{
    __shared__ float XsT[16][68];   // [k][row]
    __shared__ float WsT[16][68];   // [k][col]

    const float* W; const float* bias; float* dst;
    int z = blockIdx.z;
    if (z == 0)      { W = Wq; bias = bq; dst = g_Q; }
    else if (z == 1) { W = Wk; bias = bk; dst = g_K; }
    else             { W = Wv; bias = bv; dst = g_V; }

    const int i0 = blockIdx.x * 64;
    const int j0 = blockIdx.y * 64;
    const int t  = threadIdx.x;
    const int tx = t & 15, ty = t >> 4;
    const int lr = t >> 2, lk4 = (t & 3) * 4;

    float c[4][4];
    #pragma unroll
    for (int a = 0; a < 4; ++a)
        #pragma unroll
        for (int bb = 0; bb < 4; ++bb) c[a][bb] = 0.f;

    for (int kk = 0; kk < DMODEL; kk += 16) {
        float4 xa = *(const float4*)&x[(size_t)(i0 + lr) * DMODEL + kk + lk4];
        float4 wa = *(const float4*)&W[(size_t)(j0 + lr) * DMODEL + kk + lk4];
        XsT[lk4+0][lr] = xa.x; XsT[lk4+1][lr] = xa.y;
        XsT[lk4+2][lr] = xa.z; XsT[lk4+3][lr] = xa.w;
        WsT[lk4+0][lr] = wa.x; WsT[lk4+1][lr] = wa.y;
        WsT[lk4+2][lr] = wa.z; WsT[lk4+3][lr] = wa.w;
        __syncthreads();
        #pragma unroll
        for (int k = 0; k < 16; ++k) {
            float4 a4 = *(const float4*)&XsT[k][ty * 4];
            float4 b4 = *(const float4*)&WsT[k][tx * 4];
            float av[4] = {a4.x, a4.y, a4.z, a4.w};
            float bv4[4] = {b4.x, b4.y, b4.z, b4.w};
            #pragma unroll
            for (int ii = 0; ii < 4; ++ii)
                #pragma unroll
                for (int jj = 0; jj < 4; ++jj)
                    c[ii][jj] = fmaf(av[ii], bv4[jj], c[ii][jj]);
        }
        __syncthreads();
    }

    #pragma unroll
    for (int ii = 0; ii < 4; ++ii) {
        int i = i0 + ty * 4 + ii;
        int bb = i >> 11;               // batch
        int n  = i & (NSEQ - 1);
        #pragma unroll
        for (int jj = 0; jj < 4; ++jj) {
            int j  = j0 + tx * 4 + jj;
            int hh = j >> 5;
            int dc = j & (DH - 1);
            dst[(((size_t)bb * NH + hh) * NSEQ + n) * DH + dc] = c[ii][jj] + bias[j];
        }
    }
}

// ---------------------------------------------------------------------------
// Kernel 2: fused flash attention, 2 heads per block, 64q x 64k tiles,
// 4x4 register micro-tiles, collapsed edge-bias MLP.
//
// Thread map (256 thr): tx = t&15, ty = t>>4.
//   S tile: rows r0=ty*4 (4), cols c0=tx*4 (4), per head.
//   O tile: rows r0=ty*4 (4), concat dh col = tx*4  (head oh=tx>>3, col oc).
// Bias: b1==0 (checked) =>  bias_h(a) = b2h + Pc*a + Qc*|a|   (exact).
// ---------------------------------------------------------------------------
struct AttnSmem {
    float Qs[2][64][36];   // [head][row][d]
    float Kt[2][32][68];   // [head][d][m]   (K transposed)
    float Vs[64][72];      // [m][head*32+d] (2 heads concat)
    float Ps[2][64][68];   // [head][row][m]
};

__global__ __launch_bounds__(256) void attn_kernel(
    const float* __restrict__ A,
    const float* __restrict__ W1, const float* __restrict__ b1,
    const float* __restrict__ W2, const float* __restrict__ b2)
{
    extern __shared__ char smem_raw[];
    AttnSmem& sm = *reinterpret_cast<AttnSmem*>(smem_raw);

    const int qb = blockIdx.x, hp = blockIdx.y, b = blockIdx.z;
    const int h0 = hp * 2;
    const int q0 = qb * 64;

    const int t  = threadIdx.x;
    const int tx = t & 15, ty = t >> 4;
    const int r0 = ty * 4, c0 = tx * 4;
    const int oh = tx >> 3;            // O head within pair
    const int oc = (tx & 7) * 4;       // O dh col within head

    const float* Qg = g_Q + ((size_t)(b * NH + h0)) * NSEQ * DH;
    const float* Kg = g_K + ((size_t)(b * NH + h0)) * NSEQ * DH;
    const float* Vg = g_V + ((size_t)(b * NH + h0)) * NSEQ * DH;
    const float* Ab = A + (size_t)b * NSEQ * NSEQ;

    // ---- load Q tiles (both heads): 1024 float4, 4 per thread ----
    #pragma unroll
    for (int i = 0; i < 4; ++i) {
        int idx = i * 256 + t;
        int h2 = idx >> 9, rem = idx & 511;
        int rr = rem >> 3, d4 = (rem & 7) * 4;
        float4 v = *(const float4*)&Qg[((size_t)h2 * NSEQ + q0 + rr) * DH + d4];
        *(float4*)&sm.Qs[h2][rr][d4] = v;
    }

    // ---- bias constants (linear collapse valid iff b1 == 0) ----
    float Pc[2], Qc[2], B2[2];
    bool lin;
    {
        float ssum = 0.f;
        #pragma unroll
        for (int k = 0; k < 8; ++k) ssum += fabsf(__ldg(&b1[k]));
        lin = (ssum == 0.f);
        #pragma unroll
        for (int h2 = 0; h2 < 2; ++h2) {
            float p = 0.f, q = 0.f;
            #pragma unroll
            for (int k = 0; k < 8; ++k) {
                float w1k = __ldg(&W1[k]);
                float w2k = __ldg(&W2[(h0 + h2) * NH + k]);
                p = fmaf(w2k, w1k, p);
                q = fmaf(w2k, fabsf(w1k), q);
            }
            Pc[h2] = 0.505f * p;
            Qc[h2] = 0.495f * q;
            B2[h2] = __ldg(&b2[h0 + h2]);
        }
    }
    const float scale = 0.17677669529663687f;  // 1/sqrt(32)

    float mrow[2][4], lrow[2][4], acc[4][4];
    #pragma unroll
    for (int h2 = 0; h2 < 2; ++h2)
        #pragma unroll
        for (int i = 0; i < 4; ++i) { mrow[h2][i] = -3.4e38f; lrow[h2][i] = 0.f; }
    #pragma unroll
    for (int i = 0; i < 4; ++i)
        #pragma unroll
        for (int j = 0; j < 4; ++j) acc[i][j] = 0.f;

    for (int m0 = 0; m0 < NSEQ; m0 += 64) {
        __syncthreads();  // prev PV done (and Q visible on first iter)

        // ---- load K (transposed) + V (concat) tiles: 4 float4 each ----
        #pragma unroll
        for (int i = 0; i < 4; ++i) {
            int idx = i * 256 + t;
            int h2 = idx >> 9, rem = idx & 511;
            int mm = rem >> 3, d4 = (rem & 7) * 4;
            float4 kv = *(const float4*)&Kg[((size_t)h2 * NSEQ + m0 + mm) * DH + d4];
            sm.Kt[h2][d4 + 0][mm] = kv.x; sm.Kt[h2][d4 + 1][mm] = kv.y;
            sm.Kt[h2][d4 + 2][mm] = kv.z; sm.Kt[h2][d4 + 3][mm] = kv.w;
            float4 vv = *(const float4*)&Vg[((size_t)h2 * NSEQ + m0 + mm) * DH + d4];
            *(float4*)&sm.Vs[mm][h2 * DH + d4] = vv;
        }
        __syncthreads();

        // ---- S = Q K^T : 4x4 micro-tile per head ----
        float s[2][4][4];
        #pragma unroll
        for (int h2 = 0; h2 < 2; ++h2)
            #pragma unroll
            for (int i = 0; i < 4; ++i)
                #pragma unroll
                for (int j = 0; j < 4; ++j) s[h2][i][j] = 0.f;

        #pragma unroll 2
        for (int d = 0; d < DH; d += 4) {
            #pragma unroll
            for (int h2 = 0; h2 < 2; ++h2) {
                float4 q4[4];
                #pragma unroll
                for (int i = 0; i < 4; ++i)
                    q4[i] = *(const float4*)&sm.Qs[h2][r0 + i][d];
                #pragma unroll
                for (int dd = 0; dd < 4; ++dd) {
                    float4 kv = *(const float4*)&sm.Kt[h2][d + dd][c0];
                    float kf[4] = {kv.x, kv.y, kv.z, kv.w};
                    #pragma unroll
                    for (int i = 0; i < 4; ++i) {
                        float qv = ((const float*)&q4[i])[dd];
                        #pragma unroll
                        for (int j = 0; j < 4; ++j)
                            s[h2][i][j] = fmaf(qv, kf[j], s[h2][i][j]);
                    }
                }
            }
        }

        // ---- edge bias (A loads shared by both heads) ----
        #pragma unroll
        for (int i = 0; i < 4; ++i) {
            float4 a4 = *(const float4*)&Ab[(size_t)(q0 + r0 + i) * NSEQ + m0 + c0];
            float af[4] = {a4.x, a4.y, a4.z, a4.w};
            if (lin) {
                #pragma unroll
                for (int h2 = 0; h2 < 2; ++h2)
                    #pragma unroll
                    for (int j = 0; j < 4; ++j) {
                        float bia = fmaf(Pc[h2], af[j], B2[h2]);
                        bia = fmaf(Qc[h2], fabsf(af[j]), bia);
                        s[h2][i][j] = fmaf(s[h2][i][j], scale, bia);
                    }
            } else {
                #pragma unroll
                for (int h2 = 0; h2 < 2; ++h2)
                    #pragma unroll
                    for (int j = 0; j < 4; ++j) {
                        float bia = __ldg(&b2[h0 + h2]);
                        for (int k = 0; k < 8; ++k) {
                            float zz = fmaf(af[j], __ldg(&W1[k]), __ldg(&b1[k]));
                            float hk = fmaxf(zz, 0.01f * zz);
                            bia = fmaf(__ldg(&W2[(h0 + h2) * NH + k]), hk, bia);
                        }
                        s[h2][i][j] = fmaf(s[h2][i][j], scale, bia);
                    }
            }
        }

        // ---- online softmax (16 tx-lanes per row cooperate via shfl) ----
        float alpha2[2][4];
        #pragma unroll
        for (int h2 = 0; h2 < 2; ++h2) {
            #pragma unroll
            for (int i = 0; i < 4; ++i) {
                float tmax = fmaxf(fmaxf(s[h2][i][0], s[h2][i][1]),
                                   fmaxf(s[h2][i][2], s[h2][i][3]));
                tmax = fmaxf(tmax, __shfl_xor_sync(0xffffffffu, tmax, 1));
                tmax = fmaxf(tmax, __shfl_xor_sync(0xffffffffu, tmax, 2));
                tmax = fmaxf(tmax, __shfl_xor_sync(0xffffffffu, tmax, 4));
                tmax = fmaxf(tmax, __shfl_xor_sync(0xffffffffu, tmax, 8));
                float mnew = fmaxf(mrow[h2][i], tmax);
                float al   = __expf(mrow[h2][i] - mnew);
                float tsum = 0.f;
                #pragma unroll
                for (int j = 0; j < 4; ++j) {
                    s[h2][i][j] = __expf(s[h2][i][j] - mnew);
                    tsum += s[h2][i][j];
                }
                tsum += __shfl_xor_sync(0xffffffffu, tsum, 1);
                tsum += __shfl_xor_sync(0xffffffffu, tsum, 2);
                tsum += __shfl_xor_sync(0xffffffffu, tsum, 4);
                tsum += __shfl_xor_sync(0xffffffffu, tsum, 8);
                lrow[h2][i] = lrow[h2][i] * al + tsum;
                mrow[h2][i] = mnew;
                alpha2[h2][i] = al;
            }
        }

        // ---- store P, rescale O accumulators ----
        #pragma unroll
        for (int h2 = 0; h2 < 2; ++h2)
            #pragma unroll
            for (int i = 0; i < 4; ++i)
                *(float4*)&sm.Ps[h2][r0 + i][c0] =
                    make_float4(s[h2][i][0], s[h2][i][1], s[h2][i][2], s[h2][i][3]);
        #pragma unroll
        for (int i = 0; i < 4; ++i) {
            float al = alpha2[oh][i];
            #pragma unroll
            for (int j = 0; j < 4; ++j) acc[i][j] *= al;
        }
        __syncthreads();

        // ---- O += P V  (thread: 4 rows x 4 dh cols of its head) ----
        #pragma unroll 4
        for (int mc = 0; mc < 64; mc += 4) {
            float4 p4[4];
            #pragma unroll
            for (int i = 0; i < 4; ++i)
                p4[i] = *(const float4*)&sm.Ps[oh][r0 + i][mc];
            #pragma unroll
            for (int mm = 0; mm < 4; ++mm) {
                float4 vv = *(const float4*)&sm.Vs[mc + mm][oh * DH + oc];
                float vf[4] = {vv.x, vv.y, vv.z, vv.w};
                #pragma unroll
                for (int i = 0; i < 4; ++i) {
                    float pv = ((const float*)&p4[i])[mm];
                    #pragma unroll
                    for (int j = 0; j < 4; ++j)
                        acc[i][j] = fmaf(pv, vf[j], acc[i][j]);
                }
            }
        }
    }

    // ---- epilogue: normalize, write (b,n,D) ----
    #pragma unroll
    for (int i = 0; i < 4; ++i) {
        float inv = 1.f / lrow[oh][i];
        float* op = g_att + ((size_t)b * NSEQ + q0 + r0 + i) * DMODEL + (h0 + oh) * DH + oc;
        *(float4*)op = make_float4(acc[i][0] * inv, acc[i][1] * inv,
                                   acc[i][2] * inv, acc[i][3] * inv);
    }
}

// ---------------------------------------------------------------------------
// Kernel 3: output projection.  out = att @ Wo^T + bo.
// ---------------------------------------------------------------------------
__global__ __launch_bounds__(256) void out_proj_kernel(
    const float* __restrict__ Wo, const float* __restrict__ bo,
    float* __restrict__ out)
{
    __shared__ float XsT[16][68];
    __shared__ float WsT[16][68];

    const int i0 = blockIdx.x * 64;
    const int j0 = blockIdx.y * 64;
    const int t  = threadIdx.x;
    const int tx = t & 15, ty = t >> 4;
    const int lr = t >> 2, lk4 = (t & 3) * 4;

    float c[4][4];
    #pragma unroll
    for (int a = 0; a < 4; ++a)
        #pragma unroll
        for (int bb = 0; bb < 4; ++bb) c[a][bb] = 0.f;

    for (int kk = 0; kk < DMODEL; kk += 16) {
        float4 xa = *(const float4*)&g_att[(size_t)(i0 + lr) * DMODEL + kk + lk4];
        float4 wa = *(const float4*)&Wo[(size_t)(j0 + lr) * DMODEL + kk + lk4];
        XsT[lk4+0][lr] = xa.x; XsT[lk4+1][lr] = xa.y;
        XsT[lk4+2][lr] = xa.z; XsT[lk4+3][lr] = xa.w;
        WsT[lk4+0][lr] = wa.x; WsT[lk4+1][lr] = wa.y;
        WsT[lk4+2][lr] = wa.z; WsT[lk4+3][lr] = wa.w;
        __syncthreads();
        #pragma unroll
        for (int k = 0; k < 16; ++k) {
            float4 a4 = *(const float4*)&XsT[k][ty * 4];
            float4 b4 = *(const float4*)&WsT[k][tx * 4];
            float av[4] = {a4.x, a4.y, a4.z, a4.w};
            float bv4[4] = {b4.x, b4.y, b4.z, b4.w};
            #pragma unroll
            for (int ii = 0; ii < 4; ++ii)
                #pragma unroll
                for (int jj = 0; jj < 4; ++jj)
                    c[ii][jj] = fmaf(av[ii], bv4[jj], c[ii][jj]);
        }
        __syncthreads();
    }

    #pragma unroll
    for (int ii = 0; ii < 4; ++ii) {
        int i = i0 + ty * 4 + ii;
        #pragma unroll
        for (int jj = 0; jj < 4; ++jj) {
            int j = j0 + tx * 4 + jj;
            out[(size_t)i * DMODEL + j] = c[ii][jj] + bo[j];
        }
    }
}

// ---------------------------------------------------------------------------
extern "C" void kernel_launch(void* const* d_in, const int* in_sizes, int n_in,
                              void* d_out, int out_size)
{
    const float* x  = (const float*)d_in[0];
    const float* A  = (const float*)d_in[1];
    const float* Wq = (const float*)d_in[2];
    const float* bq = (const float*)d_in[3];
    const float* Wk = (const float*)d_in[4];
    const float* bk = (const float*)d_in[5];
    const float* Wv = (const float*)d_in[6];
    const float* bv = (const float*)d_in[7];
    const float* Wo = (const float*)d_in[8];
    const float* bo = (const float*)d_in[9];
    const float* W1 = (const float*)d_in[10];
    const float* b1 = (const float*)d_in[11];
    const float* W2 = (const float*)d_in[12];
    const float* b2 = (const float*)d_in[13];
    float* out = (float*)d_out;

    dim3 gProj(BNROWS / 64, DMODEL / 64, 3);
    qkv_proj_kernel<<<gProj, 256>>>(x, Wq, bq, Wk, bk, Wv, bv);

    cudaFuncSetAttribute(attn_kernel, cudaFuncAttributeMaxDynamicSharedMemorySize,
                         (int)sizeof(AttnSmem));
    dim3 gAttn(NSEQ / 64, NH / 2, NB);
    attn_kernel<<<gAttn, 256, sizeof(AttnSmem)>>>(A, W1, b1, W2, b2);

    dim3 gOut(BNROWS / 64, DMODEL / 64);
    out_proj_kernel<<<gOut, 256>>>(Wo, bo, out);
}